// round 16
// baseline (speedup 1.0000x reference)
#include <cuda_runtime.h>
#include <cuda_fp16.h>
#include <cstdint>
#include <math.h>

#define SEQ 2048
#define MR  4096

// ---------------- scratch (device globals; no allocs) ----------------
__device__ __half g_xh [MR*1024];           // x -> fp16
__device__ __half g_wh [3*1024*1024];       // qkv_w -> fp16
__device__ __half g_pwh[1024*1024];         // proj_w -> fp16
__device__ __half g_qkv[(size_t)MR*3072];   // q(*0.125)|k|v fp16, row-major [s][3072]
__device__ __half g_ctx[(size_t)MR*1024];   // attention out fp16

// ---------------- helpers ----------------
__device__ __forceinline__ uint32_t sm_u32(const void* p){
    uint32_t a;
    asm("{ .reg .u64 t; cvta.to.shared.u64 t, %1; cvt.u32.u64 %0, t; }" : "=r"(a) : "l"(p));
    return a;
}
__device__ __forceinline__ uint32_t h2u(float x, float y){
    __half2 h = __float22half2_rn(make_float2(x, y));
    return *(uint32_t*)&h;
}
#define CP16(dst,src) asm volatile("cp.async.cg.shared.global [%0], [%1], 16;" :: "r"(dst),"l"(src))
#define CPC()  asm volatile("cp.async.commit_group;")
#define CPW(n) asm volatile("cp.async.wait_group %0;" :: "n"(n))

__device__ __forceinline__ void mma16(float* c, const uint32_t* a, const uint32_t* b){
    asm volatile("mma.sync.aligned.m16n8k16.row.col.f32.f16.f16.f32 "
        "{%0,%1,%2,%3}, {%4,%5,%6,%7}, {%8,%9}, {%0,%1,%2,%3};"
        : "+f"(c[0]),"+f"(c[1]),"+f"(c[2]),"+f"(c[3])
        : "r"(a[0]),"r"(a[1]),"r"(a[2]),"r"(a[3]), "r"(b[0]),"r"(b[1]));
}
__device__ __forceinline__ void ldsm4(uint32_t* r, uint32_t a){
    asm volatile("ldmatrix.sync.aligned.m8n8.x4.shared.b16 {%0,%1,%2,%3}, [%4];"
        : "=r"(r[0]),"=r"(r[1]),"=r"(r[2]),"=r"(r[3]) : "r"(a));
}
__device__ __forceinline__ void ldsm4t(uint32_t* r, uint32_t a){
    asm volatile("ldmatrix.sync.aligned.m8n8.x4.trans.shared.b16 {%0,%1,%2,%3}, [%4];"
        : "=r"(r[0]),"=r"(r[1]),"=r"(r[2]),"=r"(r[3]) : "r"(a));
}

// ---------------------------------------------------------------------------
// fp32 -> fp16 convert (fused, single launch). index ranges select target.
// ---------------------------------------------------------------------------
__global__ void convh(const float4* __restrict__ x4, const float4* __restrict__ w4,
                      const float4* __restrict__ pw4)
{
    int i = blockIdx.x * blockDim.x + threadIdx.x;
    const float4* src; __half2* dst; int j;
    if (i < 1048576)      { src = x4;  dst = (__half2*)g_xh;  j = i; }
    else if (i < 1835008) { src = w4;  dst = (__half2*)g_wh;  j = i - 1048576; }
    else                  { src = pw4; dst = (__half2*)g_pwh; j = i - 1835008; }
    float4 v = src[j];
    dst[2*j]   = __float22half2_rn(make_float2(v.x, v.y));
    dst[2*j+1] = __float22half2_rn(make_float2(v.z, v.w));
}

// ---------------------------------------------------------------------------
// fp16 mma.sync GEMM (unchanged from R15): C[M,N] = A[M,1024] @ B[N,1024]^T + bias
// CTA 128x128, warp tile 32x64 (4x2 warps), BK=64 halves, 3-stage cp.async.
// 256 thr, 2 CTAs/SM. dyn smem: A 3*16K | B 3*16K = 98304 B.
// MODE 1: A=g_xh, B=g_wh, N=3072 -> g_qkv fp16 (q cols *0.125)
// MODE 2: A=g_ctx, B=g_pwh, N=1024 -> C fp32
// ---------------------------------------------------------------------------
template<int MODE>
__global__ __launch_bounds__(256, 2)
void mm_h(const float* __restrict__ bias, float* __restrict__ C)
{
    extern __shared__ char smem[];
    const int N = (MODE==1) ? 3072 : 1024;
    uint32_t ab = sm_u32(smem);
    uint32_t bb = ab + 49152;
    const __half* Ap = (MODE==1) ? g_xh : g_ctx;
    const __half* Bp = (MODE==1) ? g_wh : g_pwh;

    int tid = threadIdx.x, wid = tid>>5, lane = tid&31;
    int g = lane>>2, tg = lane&3;
    int wm = wid&3, wn = wid>>2;
    int bm = blockIdx.y*128, bn = blockIdx.x*128;

    auto aaddr = [&](int st,int r,int c){ return ab + st*16384 + r*128 + ((c ^ (r&7))<<4); };
    auto baddr = [&](int st,int r,int c){ return bb + st*16384 + r*128 + ((c ^ (r&7))<<4); };

    auto pf = [&](int kt, int st){
#pragma unroll
        for (int j=0;j<4;j++){
            int ci = j*256 + tid, r = ci>>3, c = ci&7;
            CP16(aaddr(st,r,c), Ap + (size_t)(bm+r)*1024 + kt*64 + c*8);
        }
#pragma unroll
        for (int j=0;j<4;j++){
            int ci = j*256 + tid, r = ci>>3, c = ci&7;
            CP16(baddr(st,r,c), Bp + (size_t)(bn+r)*1024 + kt*64 + c*8);
        }
    };

    float acc[2][8][4];
#pragma unroll
    for (int mt=0;mt<2;mt++)
#pragma unroll
        for (int nt=0;nt<8;nt++)
#pragma unroll
            for (int q=0;q<4;q++) acc[mt][nt][q] = 0.f;

    pf(0,0); CPC();
    pf(1,1); CPC();
    for (int kt=0; kt<16; kt++){
        int st = kt % 3;
        CPW(1);
        __syncthreads();
        if (kt+2 < 16) pf(kt+2, (kt+2)%3);
        CPC();
#pragma unroll
        for (int ks=0;ks<4;ks++){
            uint32_t a[2][4], b2[8][2];
#pragma unroll
            for (int mt=0;mt<2;mt++){
                int r = wm*32 + mt*16 + (lane&15);
                int c = ks*2 + ((lane>>4)&1);
                ldsm4(a[mt], aaddr(st,r,c));
            }
#pragma unroll
            for (int np=0;np<4;np++){
                int r = wn*64 + np*16 + (lane&7) + ((lane>>4)&1)*8;
                int c = ks*2 + ((lane>>3)&1);
                uint32_t t4[4];
                ldsm4(t4, baddr(st,r,c));
                b2[2*np][0]=t4[0];   b2[2*np][1]=t4[1];
                b2[2*np+1][0]=t4[2]; b2[2*np+1][1]=t4[3];
            }
#pragma unroll
            for (int mt=0;mt<2;mt++)
#pragma unroll
                for (int nt=0;nt<8;nt++)
                    mma16(acc[mt][nt], a[mt], b2[nt]);
        }
    }

#pragma unroll
    for (int mt=0;mt<2;mt++){
        int r0 = bm + wm*32 + mt*16 + g;
#pragma unroll
        for (int nt=0;nt<8;nt++){
            int c0 = bn + wn*64 + nt*8 + 2*tg;
            float b0 = bias[c0], b1 = bias[c0+1];
            float v0 = acc[mt][nt][0]+b0, v1 = acc[mt][nt][1]+b1;
            float v2 = acc[mt][nt][2]+b0, v3 = acc[mt][nt][3]+b1;
            if (MODE==1){
                float sc = (c0 < 1024) ? 0.125f : 1.f;       // fold 1/sqrt(64) into q
                *(__half2*)&g_qkv[(size_t)r0*3072 + c0]     = __float22half2_rn(make_float2(v0*sc, v1*sc));
                *(__half2*)&g_qkv[(size_t)(r0+8)*3072 + c0] = __float22half2_rn(make_float2(v2*sc, v3*sc));
            } else {
                *(float2*)&C[(size_t)r0*N + c0]     = make_float2(v0,v1);
                *(float2*)&C[(size_t)(r0+8)*N + c0] = make_float2(v2,v3);
            }
        }
    }
}

// ---------------------------------------------------------------------------
// Flash attention, fp16 mma.sync. CTA = 256 queries of one (b,h), 256 thr,
// 8 warps x 32 rows. Bc=64 keys/iter, 32 iters. 2 CTAs/SM (single wave).
// P stays IN REGISTERS: S-accum C-layout == PV A-fragment layout (cvt only).
// dyn smem: Q[256x128B] 32768 | K 2x8192 | V 2x8192 = 65536
// ---------------------------------------------------------------------------
__global__ __launch_bounds__(256, 2)
void attn_h()
{
    extern __shared__ char smem[];
    uint32_t sb = sm_u32(smem);
    const uint32_t QO = 0, KO = 32768, VO = 49152;

    int tid = threadIdx.x, wid = tid>>5, lane = tid&31;
    int g = lane>>2, tg = lane&3;
    int bh = blockIdx.y, b = bh>>4, hh = bh&15;
    int q0 = blockIdx.x * 256;

    const __half* Qg  = g_qkv + (size_t)(b*2048 + q0)*3072 + hh*64;
    const __half* KVg = g_qkv + (size_t)(b*2048)*3072 + 1024 + hh*64;

    auto qaddr = [&](int r,int c){ return sb + QO + r*128 + ((c ^ (r&7))<<4); };
    auto kaddr = [&](int st,int r,int c){ return sb + KO + st*8192 + r*128 + ((c ^ (r&7))<<4); };
    auto vaddr = [&](int st,int r,int c){ return sb + VO + st*8192 + r*128 + ((c ^ (r&7))<<4); };

    // Q tile: 256 rows x 8 chunks = 2048 cp16, 8/thread
#pragma unroll
    for (int j=0;j<8;j++){
        int ci = j*256 + tid, r = ci>>3, c = ci&7;
        CP16(qaddr(r,c), Qg + (size_t)r*3072 + c*8);
    }
    auto pf = [&](int it, int st){
        int kt = it * 64;
#pragma unroll
        for (int j=0;j<2;j++){
            int ci = j*256 + tid, r = ci>>3, c = ci&7;
            CP16(kaddr(st,r,c), KVg + (size_t)(kt+r)*3072 + c*8);          // K
        }
#pragma unroll
        for (int j=0;j<2;j++){
            int ci = j*256 + tid, r = ci>>3, c = ci&7;
            CP16(vaddr(st,r,c), KVg + (size_t)(kt+r)*3072 + 1024 + c*8);   // V
        }
    };

    float o[2][8][4], m[2][2], l[2][2];
#pragma unroll
    for (int mt=0;mt<2;mt++){
        m[mt][0]=m[mt][1]=-1e30f; l[mt][0]=l[mt][1]=0.f;
#pragma unroll
        for (int nt=0;nt<8;nt++)
#pragma unroll
            for (int q=0;q<4;q++) o[mt][nt][q]=0.f;
    }

    pf(0,0); CPC();
    for (int it=0; it<32; it++){
        int st = it & 1;
        if (it+1 < 32){ pf(it+1, st^1); CPC(); CPW(1); } else CPW(0);
        __syncthreads();

        // ---- S = Q @ K^T : warp rows wid*32..+31, cols 0..63 ----
        float s[2][8][4];
#pragma unroll
        for (int mt=0;mt<2;mt++)
#pragma unroll
            for (int nt=0;nt<8;nt++)
#pragma unroll
                for (int q=0;q<4;q++) s[mt][nt][q]=0.f;
#pragma unroll
        for (int ks=0;ks<4;ks++){
            uint32_t a[2][4], b2[8][2];
#pragma unroll
            for (int mt=0;mt<2;mt++){
                int r = wid*32 + mt*16 + (lane&15);
                int c = ks*2 + ((lane>>4)&1);
                ldsm4(a[mt], qaddr(r,c));
            }
#pragma unroll
            for (int np=0;np<4;np++){
                int r = np*16 + (lane&7) + ((lane>>4)&1)*8;
                int c = ks*2 + ((lane>>3)&1);
                uint32_t t4[4];
                ldsm4(t4, kaddr(st,r,c));
                b2[2*np][0]=t4[0];   b2[2*np][1]=t4[1];
                b2[2*np+1][0]=t4[2]; b2[2*np+1][1]=t4[3];
            }
#pragma unroll
            for (int mt=0;mt<2;mt++)
#pragma unroll
                for (int nt=0;nt<8;nt++)
                    mma16(s[mt][nt], a[mt], b2[nt]);
        }

        // ---- online softmax: 4 row-states per thread (mt x half) ----
        float al[2][2];
#pragma unroll
        for (int mt=0;mt<2;mt++)
#pragma unroll
            for (int hf=0;hf<2;hf++){
                float mx = -1e30f;
#pragma unroll
                for (int nt=0;nt<8;nt++)
                    mx = fmaxf(mx, fmaxf(s[mt][nt][2*hf], s[mt][nt][2*hf+1]));
                mx = fmaxf(mx, __shfl_xor_sync(0xffffffffu, mx, 1));
                mx = fmaxf(mx, __shfl_xor_sync(0xffffffffu, mx, 2));
                float mn = fmaxf(m[mt][hf], mx);
                al[mt][hf] = __expf(m[mt][hf] - mn);
                m[mt][hf] = mn;
                float sum = 0.f;
#pragma unroll
                for (int nt=0;nt<8;nt++){
                    s[mt][nt][2*hf]   = __expf(s[mt][nt][2*hf]   - mn); sum += s[mt][nt][2*hf];
                    s[mt][nt][2*hf+1] = __expf(s[mt][nt][2*hf+1] - mn); sum += s[mt][nt][2*hf+1];
                }
                sum += __shfl_xor_sync(0xffffffffu, sum, 1);
                sum += __shfl_xor_sync(0xffffffffu, sum, 2);
                l[mt][hf] = l[mt][hf]*al[mt][hf] + sum;
            }
#pragma unroll
        for (int mt=0;mt<2;mt++)
#pragma unroll
            for (int nt=0;nt<8;nt++){
                o[mt][nt][0]*=al[mt][0]; o[mt][nt][1]*=al[mt][0];
                o[mt][nt][2]*=al[mt][1]; o[mt][nt][3]*=al[mt][1];
            }

        // ---- O += P @ V : P direct from registers (C-layout == A-layout) ----
#pragma unroll
        for (int ks=0;ks<4;ks++){
            uint32_t a[2][4], b2[8][2];
#pragma unroll
            for (int mt=0;mt<2;mt++){
                a[mt][0] = h2u(s[mt][2*ks  ][0], s[mt][2*ks  ][1]);
                a[mt][1] = h2u(s[mt][2*ks  ][2], s[mt][2*ks  ][3]);
                a[mt][2] = h2u(s[mt][2*ks+1][0], s[mt][2*ks+1][1]);
                a[mt][3] = h2u(s[mt][2*ks+1][2], s[mt][2*ks+1][3]);
            }
#pragma unroll
            for (int np=0;np<4;np++){
                int r = ks*16 + (lane&7) + ((lane>>3)&1)*8;
                int c = np*2 + (lane>>4);
                uint32_t t4[4];
                ldsm4t(t4, vaddr(st,r,c));
                b2[2*np][0]=t4[0];   b2[2*np][1]=t4[1];
                b2[2*np+1][0]=t4[2]; b2[2*np+1][1]=t4[3];
            }
#pragma unroll
            for (int mt=0;mt<2;mt++)
#pragma unroll
                for (int nt=0;nt<8;nt++)
                    mma16(o[mt][nt], a[mt], b2[nt]);
        }
        __syncthreads();
    }

    // ---- epilogue: normalize, convert fp16, write ctx ----
#pragma unroll
    for (int mt=0;mt<2;mt++){
        float i0 = 1.f/l[mt][0], i1 = 1.f/l[mt][1];
        int r0 = q0 + wid*32 + mt*16 + g;
        __half* Cg = g_ctx + (size_t)(b*2048 + r0)*1024 + hh*64;
#pragma unroll
        for (int nt=0;nt<8;nt++){
            int c = nt*8 + 2*tg;
            *(__half2*)&Cg[c]          = __float22half2_rn(make_float2(o[mt][nt][0]*i0, o[mt][nt][1]*i0));
            *(__half2*)&Cg[8*1024 + c] = __float22half2_rn(make_float2(o[mt][nt][2]*i1, o[mt][nt][3]*i1));
        }
    }
}

// ---------------------------------------------------------------------------
extern "C" void kernel_launch(void* const* d_in, const int* in_sizes, int n_in,
                              void* d_out, int out_size)
{
    const float* x      = (const float*)d_in[0];
    const float* qkv_w  = (const float*)d_in[1];
    const float* qkv_b  = (const float*)d_in[2];
    const float* proj_w = (const float*)d_in[3];
    const float* proj_b = (const float*)d_in[4];
    float* out = (float*)d_out;
    (void)in_sizes; (void)n_in; (void)out_size;

    const int GSM = 98304;    // GEMM: 3-stage A(16K)+B(16K)
    const int ASM = 65536;    // attention: Q + K/V double-buffered (no P smem)
    cudaFuncSetAttribute(mm_h<1>, cudaFuncAttributeMaxDynamicSharedMemorySize, GSM);
    cudaFuncSetAttribute(mm_h<2>, cudaFuncAttributeMaxDynamicSharedMemorySize, GSM);
    cudaFuncSetAttribute(attn_h,  cudaFuncAttributeMaxDynamicSharedMemorySize, ASM);

    convh<<<8192, 256>>>((const float4*)x, (const float4*)qkv_w, (const float4*)proj_w);

    mm_h<1><<<dim3(24, 32), 256, GSM>>>(qkv_b, nullptr);
    attn_h  <<<dim3( 8, 32), 256, ASM>>>();
    mm_h<2><<<dim3( 8, 32), 256, GSM>>>(proj_b, out);
}

// round 17
// speedup vs baseline: 1.2026x; 1.2026x over previous
#include <cuda_runtime.h>
#include <cuda_fp16.h>
#include <cstdint>
#include <math.h>

#define SEQ 2048
#define MR  4096

// ---------------- scratch (device globals; no allocs) ----------------
__device__ __half g_xh [MR*1024];           // x -> fp16
__device__ __half g_wh [3*1024*1024];       // qkv_w -> fp16
__device__ __half g_pwh[1024*1024];         // proj_w -> fp16
__device__ __half g_qkv[(size_t)MR*3072];   // q(*0.125)|k|v fp16, row-major [s][3072]
__device__ __half g_ctx[(size_t)MR*1024];   // attention out fp16

// ---------------- helpers ----------------
__device__ __forceinline__ uint32_t sm_u32(const void* p){
    uint32_t a;
    asm("{ .reg .u64 t; cvta.to.shared.u64 t, %1; cvt.u32.u64 %0, t; }" : "=r"(a) : "l"(p));
    return a;
}
__device__ __forceinline__ uint32_t h2u(float x, float y){
    __half2 h = __float22half2_rn(make_float2(x, y));
    return *(uint32_t*)&h;
}
#define CP16(dst,src) asm volatile("cp.async.cg.shared.global [%0], [%1], 16;" :: "r"(dst),"l"(src))
#define CPC()  asm volatile("cp.async.commit_group;")
#define CPW(n) asm volatile("cp.async.wait_group %0;" :: "n"(n))

__device__ __forceinline__ void mma16(float* c, const uint32_t* a, const uint32_t* b){
    asm volatile("mma.sync.aligned.m16n8k16.row.col.f32.f16.f16.f32 "
        "{%0,%1,%2,%3}, {%4,%5,%6,%7}, {%8,%9}, {%0,%1,%2,%3};"
        : "+f"(c[0]),"+f"(c[1]),"+f"(c[2]),"+f"(c[3])
        : "r"(a[0]),"r"(a[1]),"r"(a[2]),"r"(a[3]), "r"(b[0]),"r"(b[1]));
}
__device__ __forceinline__ void ldsm4(uint32_t* r, uint32_t a){
    asm volatile("ldmatrix.sync.aligned.m8n8.x4.shared.b16 {%0,%1,%2,%3}, [%4];"
        : "=r"(r[0]),"=r"(r[1]),"=r"(r[2]),"=r"(r[3]) : "r"(a));
}
__device__ __forceinline__ void ldsm4t(uint32_t* r, uint32_t a){
    asm volatile("ldmatrix.sync.aligned.m8n8.x4.trans.shared.b16 {%0,%1,%2,%3}, [%4];"
        : "=r"(r[0]),"=r"(r[1]),"=r"(r[2]),"=r"(r[3]) : "r"(a));
}

// ---------------------------------------------------------------------------
// fp32 -> fp16 convert (fused, single launch). index ranges select target.
// ---------------------------------------------------------------------------
__global__ void convh(const float4* __restrict__ x4, const float4* __restrict__ w4,
                      const float4* __restrict__ pw4)
{
    int i = blockIdx.x * blockDim.x + threadIdx.x;
    const float4* src; __half2* dst; int j;
    if (i < 1048576)      { src = x4;  dst = (__half2*)g_xh;  j = i; }
    else if (i < 1835008) { src = w4;  dst = (__half2*)g_wh;  j = i - 1048576; }
    else                  { src = pw4; dst = (__half2*)g_pwh; j = i - 1835008; }
    float4 v = src[j];
    dst[2*j]   = __float22half2_rn(make_float2(v.x, v.y));
    dst[2*j+1] = __float22half2_rn(make_float2(v.z, v.w));
}

// ---------------------------------------------------------------------------
// fp16 mma.sync GEMM (R15, unchanged): C[M,N] = A[M,1024] @ B[N,1024]^T + bias
// CTA 128x128, warp tile 32x64 (4x2 warps), BK=64 halves, 3-stage cp.async.
// 256 thr, 2 CTAs/SM. dyn smem: A 3*16K | B 3*16K = 98304 B.
// MODE 1: A=g_xh, B=g_wh, N=3072 -> g_qkv fp16 (q cols *0.125)
// MODE 2: A=g_ctx, B=g_pwh, N=1024 -> C fp32
// ---------------------------------------------------------------------------
template<int MODE>
__global__ __launch_bounds__(256, 2)
void mm_h(const float* __restrict__ bias, float* __restrict__ C)
{
    extern __shared__ char smem[];
    const int N = (MODE==1) ? 3072 : 1024;
    uint32_t ab = sm_u32(smem);
    uint32_t bb = ab + 49152;
    const __half* Ap = (MODE==1) ? g_xh : g_ctx;
    const __half* Bp = (MODE==1) ? g_wh : g_pwh;

    int tid = threadIdx.x, wid = tid>>5, lane = tid&31;
    int g = lane>>2, tg = lane&3;
    int wm = wid&3, wn = wid>>2;
    int bm = blockIdx.y*128, bn = blockIdx.x*128;

    auto aaddr = [&](int st,int r,int c){ return ab + st*16384 + r*128 + ((c ^ (r&7))<<4); };
    auto baddr = [&](int st,int r,int c){ return bb + st*16384 + r*128 + ((c ^ (r&7))<<4); };

    auto pf = [&](int kt, int st){
#pragma unroll
        for (int j=0;j<4;j++){
            int ci = j*256 + tid, r = ci>>3, c = ci&7;
            CP16(aaddr(st,r,c), Ap + (size_t)(bm+r)*1024 + kt*64 + c*8);
        }
#pragma unroll
        for (int j=0;j<4;j++){
            int ci = j*256 + tid, r = ci>>3, c = ci&7;
            CP16(baddr(st,r,c), Bp + (size_t)(bn+r)*1024 + kt*64 + c*8);
        }
    };

    float acc[2][8][4];
#pragma unroll
    for (int mt=0;mt<2;mt++)
#pragma unroll
        for (int nt=0;nt<8;nt++)
#pragma unroll
            for (int q=0;q<4;q++) acc[mt][nt][q] = 0.f;

    pf(0,0); CPC();
    pf(1,1); CPC();
    for (int kt=0; kt<16; kt++){
        int st = kt % 3;
        CPW(1);
        __syncthreads();
        if (kt+2 < 16) pf(kt+2, (kt+2)%3);
        CPC();
#pragma unroll
        for (int ks=0;ks<4;ks++){
            uint32_t a[2][4], b2[8][2];
#pragma unroll
            for (int mt=0;mt<2;mt++){
                int r = wm*32 + mt*16 + (lane&15);
                int c = ks*2 + ((lane>>4)&1);
                ldsm4(a[mt], aaddr(st,r,c));
            }
#pragma unroll
            for (int np=0;np<4;np++){
                int r = wn*64 + np*16 + (lane&7) + ((lane>>4)&1)*8;
                int c = ks*2 + ((lane>>3)&1);
                uint32_t t4[4];
                ldsm4(t4, baddr(st,r,c));
                b2[2*np][0]=t4[0];   b2[2*np][1]=t4[1];
                b2[2*np+1][0]=t4[2]; b2[2*np+1][1]=t4[3];
            }
#pragma unroll
            for (int mt=0;mt<2;mt++)
#pragma unroll
                for (int nt=0;nt<8;nt++)
                    mma16(acc[mt][nt], a[mt], b2[nt]);
        }
    }

#pragma unroll
    for (int mt=0;mt<2;mt++){
        int r0 = bm + wm*32 + mt*16 + g;
#pragma unroll
        for (int nt=0;nt<8;nt++){
            int c0 = bn + wn*64 + nt*8 + 2*tg;
            float b0 = bias[c0], b1 = bias[c0+1];
            float v0 = acc[mt][nt][0]+b0, v1 = acc[mt][nt][1]+b1;
            float v2 = acc[mt][nt][2]+b0, v3 = acc[mt][nt][3]+b1;
            if (MODE==1){
                float sc = (c0 < 1024) ? 0.125f : 1.f;       // fold 1/sqrt(64) into q
                *(__half2*)&g_qkv[(size_t)r0*3072 + c0]     = __float22half2_rn(make_float2(v0*sc, v1*sc));
                *(__half2*)&g_qkv[(size_t)(r0+8)*3072 + c0] = __float22half2_rn(make_float2(v2*sc, v3*sc));
            } else {
                *(float2*)&C[(size_t)r0*N + c0]     = make_float2(v0,v1);
                *(float2*)&C[(size_t)(r0+8)*N + c0] = make_float2(v2,v3);
            }
        }
    }
}

// ---------------------------------------------------------------------------
// Flash attention, fp16 mma.sync. CTA = 256 queries of one (b,h), 256 thr,
// 8 warps x 32 rows. Bc=64 keys/iter, 32 iters. occupancy 1 (regs free, no spills).
// P stays IN REGISTERS: S-accum C-layout == PV A-fragment layout (cvt only).
// dyn smem: Q[256x128B] 32768 | K 2x8192 | V 2x8192 = 65536
// ---------------------------------------------------------------------------
__global__ __launch_bounds__(256, 1)
void attn_h()
{
    extern __shared__ char smem[];
    uint32_t sb = sm_u32(smem);
    const uint32_t QO = 0, KO = 32768, VO = 49152;

    int tid = threadIdx.x, wid = tid>>5, lane = tid&31;
    int g = lane>>2, tg = lane&3;
    int bh = blockIdx.y, b = bh>>4, hh = bh&15;
    int q0 = blockIdx.x * 256;

    const __half* Qg  = g_qkv + (size_t)(b*2048 + q0)*3072 + hh*64;
    const __half* KVg = g_qkv + (size_t)(b*2048)*3072 + 1024 + hh*64;

    auto qaddr = [&](int r,int c){ return sb + QO + r*128 + ((c ^ (r&7))<<4); };
    auto kaddr = [&](int st,int r,int c){ return sb + KO + st*8192 + r*128 + ((c ^ (r&7))<<4); };
    auto vaddr = [&](int st,int r,int c){ return sb + VO + st*8192 + r*128 + ((c ^ (r&7))<<4); };

    // Q tile: 256 rows x 8 chunks = 2048 cp16, 8/thread
#pragma unroll
    for (int j=0;j<8;j++){
        int ci = j*256 + tid, r = ci>>3, c = ci&7;
        CP16(qaddr(r,c), Qg + (size_t)r*3072 + c*8);
    }
    auto pf = [&](int it, int st){
        int kt = it * 64;
#pragma unroll
        for (int j=0;j<2;j++){
            int ci = j*256 + tid, r = ci>>3, c = ci&7;
            CP16(kaddr(st,r,c), KVg + (size_t)(kt+r)*3072 + c*8);          // K
        }
#pragma unroll
        for (int j=0;j<2;j++){
            int ci = j*256 + tid, r = ci>>3, c = ci&7;
            CP16(vaddr(st,r,c), KVg + (size_t)(kt+r)*3072 + 1024 + c*8);   // V
        }
    };

    float o[2][8][4], m[2][2], l[2][2];
#pragma unroll
    for (int mt=0;mt<2;mt++){
        m[mt][0]=m[mt][1]=-1e30f; l[mt][0]=l[mt][1]=0.f;
#pragma unroll
        for (int nt=0;nt<8;nt++)
#pragma unroll
            for (int q=0;q<4;q++) o[mt][nt][q]=0.f;
    }

    pf(0,0); CPC();
    for (int it=0; it<32; it++){
        int st = it & 1;
        if (it+1 < 32){ pf(it+1, st^1); CPC(); CPW(1); } else CPW(0);
        __syncthreads();

        // ---- S = Q @ K^T : warp rows wid*32..+31, cols 0..63 ----
        float s[2][8][4];
#pragma unroll
        for (int mt=0;mt<2;mt++)
#pragma unroll
            for (int nt=0;nt<8;nt++)
#pragma unroll
                for (int q=0;q<4;q++) s[mt][nt][q]=0.f;
#pragma unroll
        for (int ks=0;ks<4;ks++){
            uint32_t a[2][4], b2[8][2];
#pragma unroll
            for (int mt=0;mt<2;mt++){
                int r = wid*32 + mt*16 + (lane&15);
                int c = ks*2 + ((lane>>4)&1);
                ldsm4(a[mt], qaddr(r,c));
            }
#pragma unroll
            for (int np=0;np<4;np++){
                int r = np*16 + (lane&7) + ((lane>>4)&1)*8;
                int c = ks*2 + ((lane>>3)&1);
                uint32_t t4[4];
                ldsm4(t4, kaddr(st,r,c));
                b2[2*np][0]=t4[0];   b2[2*np][1]=t4[1];
                b2[2*np+1][0]=t4[2]; b2[2*np+1][1]=t4[3];
            }
#pragma unroll
            for (int mt=0;mt<2;mt++)
#pragma unroll
                for (int nt=0;nt<8;nt++)
                    mma16(s[mt][nt], a[mt], b2[nt]);
        }

        // ---- online softmax: 4 row-states per thread (mt x half) ----
        float al[2][2];
#pragma unroll
        for (int mt=0;mt<2;mt++)
#pragma unroll
            for (int hf=0;hf<2;hf++){
                float mx = -1e30f;
#pragma unroll
                for (int nt=0;nt<8;nt++)
                    mx = fmaxf(mx, fmaxf(s[mt][nt][2*hf], s[mt][nt][2*hf+1]));
                mx = fmaxf(mx, __shfl_xor_sync(0xffffffffu, mx, 1));
                mx = fmaxf(mx, __shfl_xor_sync(0xffffffffu, mx, 2));
                float mn = fmaxf(m[mt][hf], mx);
                al[mt][hf] = __expf(m[mt][hf] - mn);
                m[mt][hf] = mn;
                float sum = 0.f;
#pragma unroll
                for (int nt=0;nt<8;nt++){
                    s[mt][nt][2*hf]   = __expf(s[mt][nt][2*hf]   - mn); sum += s[mt][nt][2*hf];
                    s[mt][nt][2*hf+1] = __expf(s[mt][nt][2*hf+1] - mn); sum += s[mt][nt][2*hf+1];
                }
                sum += __shfl_xor_sync(0xffffffffu, sum, 1);
                sum += __shfl_xor_sync(0xffffffffu, sum, 2);
                l[mt][hf] = l[mt][hf]*al[mt][hf] + sum;
            }
#pragma unroll
        for (int mt=0;mt<2;mt++)
#pragma unroll
            for (int nt=0;nt<8;nt++){
                o[mt][nt][0]*=al[mt][0]; o[mt][nt][1]*=al[mt][0];
                o[mt][nt][2]*=al[mt][1]; o[mt][nt][3]*=al[mt][1];
            }

        // ---- O += P @ V : P direct from registers (C-layout == A-layout) ----
#pragma unroll
        for (int ks=0;ks<4;ks++){
            uint32_t a[2][4], b2[8][2];
#pragma unroll
            for (int mt=0;mt<2;mt++){
                a[mt][0] = h2u(s[mt][2*ks  ][0], s[mt][2*ks  ][1]);
                a[mt][1] = h2u(s[mt][2*ks  ][2], s[mt][2*ks  ][3]);
                a[mt][2] = h2u(s[mt][2*ks+1][0], s[mt][2*ks+1][1]);
                a[mt][3] = h2u(s[mt][2*ks+1][2], s[mt][2*ks+1][3]);
            }
#pragma unroll
            for (int np=0;np<4;np++){
                int r = ks*16 + (lane&7) + ((lane>>3)&1)*8;
                int c = np*2 + (lane>>4);
                uint32_t t4[4];
                ldsm4t(t4, vaddr(st,r,c));
                b2[2*np][0]=t4[0];   b2[2*np][1]=t4[1];
                b2[2*np+1][0]=t4[2]; b2[2*np+1][1]=t4[3];
            }
#pragma unroll
            for (int mt=0;mt<2;mt++)
#pragma unroll
                for (int nt=0;nt<8;nt++)
                    mma16(o[mt][nt], a[mt], b2[nt]);
        }
        __syncthreads();
    }

    // ---- epilogue: normalize, convert fp16, write ctx ----
#pragma unroll
    for (int mt=0;mt<2;mt++){
        float i0 = 1.f/l[mt][0], i1 = 1.f/l[mt][1];
        int r0 = q0 + wid*32 + mt*16 + g;
        __half* Cg = g_ctx + (size_t)(b*2048 + r0)*1024 + hh*64;
#pragma unroll
        for (int nt=0;nt<8;nt++){
            int c = nt*8 + 2*tg;
            *(__half2*)&Cg[c]          = __float22half2_rn(make_float2(o[mt][nt][0]*i0, o[mt][nt][1]*i0));
            *(__half2*)&Cg[8*1024 + c] = __float22half2_rn(make_float2(o[mt][nt][2]*i1, o[mt][nt][3]*i1));
        }
    }
}

// ---------------------------------------------------------------------------
extern "C" void kernel_launch(void* const* d_in, const int* in_sizes, int n_in,
                              void* d_out, int out_size)
{
    const float* x      = (const float*)d_in[0];
    const float* qkv_w  = (const float*)d_in[1];
    const float* qkv_b  = (const float*)d_in[2];
    const float* proj_w = (const float*)d_in[3];
    const float* proj_b = (const float*)d_in[4];
    float* out = (float*)d_out;
    (void)in_sizes; (void)n_in; (void)out_size;

    const int GSM = 98304;    // GEMM: 3-stage A(16K)+B(16K)
    const int ASM = 65536;    // attention: Q + K/V double-buffered (no P smem)
    cudaFuncSetAttribute(mm_h<1>, cudaFuncAttributeMaxDynamicSharedMemorySize, GSM);
    cudaFuncSetAttribute(mm_h<2>, cudaFuncAttributeMaxDynamicSharedMemorySize, GSM);
    cudaFuncSetAttribute(attn_h,  cudaFuncAttributeMaxDynamicSharedMemorySize, ASM);

    convh<<<8192, 256>>>((const float4*)x, (const float4*)qkv_w, (const float4*)proj_w);

    mm_h<1><<<dim3(24, 32), 256, GSM>>>(qkv_b, nullptr);
    attn_h  <<<dim3( 8, 32), 256, ASM>>>();
    mm_h<2><<<dim3( 8, 32), 256, GSM>>>(proj_b, out);
}